// round 9
// baseline (speedup 1.0000x reference)
#include <cuda_runtime.h>
#include <cstdint>
#include <math.h>

#define BROWS 4096
#define DIN   2048
#define DHID  3584
#define DOUT  2048

// ---------------- scratch (static __device__, no allocation) ----------------
__device__ float g_scale[BROWS];
__device__ int   g_mx, g_mwf, g_mwm, g_mwe, g_mxe;   // float-bits absmax (>=0)
__device__ __align__(16) uint8_t g_qx1 [(size_t)BROWS*DIN];
__device__ __align__(16) uint8_t g_qx2 [(size_t)BROWS*DIN];
__device__ __align__(16) uint8_t g_qwf1[(size_t)DHID*DIN];
__device__ __align__(16) uint8_t g_qwf2[(size_t)DHID*DIN];
__device__ __align__(16) uint8_t g_qwm1[(size_t)DOUT*DHID];
__device__ __align__(16) uint8_t g_qwm2[(size_t)DOUT*DHID];
__device__ __align__(16) uint8_t g_qwe1[(size_t)DOUT*DHID];   // flipped female
__device__ __align__(16) uint8_t g_qwe2[(size_t)DOUT*DHID];
__device__ __align__(16) uint8_t g_qxe1[(size_t)BROWS*DHID];
__device__ __align__(16) uint8_t g_qxe2[(size_t)BROWS*DHID];
__device__ __align__(16) float   g_xef [(size_t)BROWS*DHID];  // fp32 x_expanded
__device__ __align__(16) float   g_male[(size_t)BROWS*DOUT];
__device__ __align__(16) float   g_fem [(size_t)BROWS*DOUT];

// ---------------- PTX helpers ----------------
__device__ __forceinline__ uint32_t smem_u32(const void* p) {
    uint32_t a;
    asm("{ .reg .u64 t; cvta.to.shared.u64 t, %1; cvt.u32.u64 %0, t; }" : "=r"(a) : "l"(p));
    return a;
}
#define CP16(dst, src) asm volatile("cp.async.cg.shared.global [%0], [%1], 16;" :: "r"(dst), "l"(src))
#define CP_COMMIT()    asm volatile("cp.async.commit_group;" ::: "memory")
#define CP_WAIT1()     asm volatile("cp.async.wait_group 1;" ::: "memory")
#define CP_WAIT0()     asm volatile("cp.async.wait_group 0;" ::: "memory")

__device__ __forceinline__ void ldsm4(uint32_t* r, uint32_t addr) {
    asm volatile("ldmatrix.sync.aligned.m8n8.x4.shared.b16 {%0,%1,%2,%3}, [%4];"
                 : "=r"(r[0]), "=r"(r[1]), "=r"(r[2]), "=r"(r[3]) : "r"(addr));
}
__device__ __forceinline__ void ldsm2(uint32_t* r, uint32_t addr) {
    asm volatile("ldmatrix.sync.aligned.m8n8.x2.shared.b16 {%0,%1}, [%2];"
                 : "=r"(r[0]), "=r"(r[1]) : "r"(addr));
}
__device__ __forceinline__ void mma_s8(int* c, const uint32_t* a, const uint32_t* b) {
    asm volatile(
        "mma.sync.aligned.m16n8k32.row.col.s32.s8.s8.s32 "
        "{%0,%1,%2,%3}, {%4,%5,%6,%7}, {%8,%9}, {%0,%1,%2,%3};"
        : "+r"(c[0]), "+r"(c[1]), "+r"(c[2]), "+r"(c[3])
        : "r"(a[0]), "r"(a[1]), "r"(a[2]), "r"(a[3]), "r"(b[0]), "r"(b[1]));
}
// per-byte arithmetic >>4 on packed s8x4
__device__ __forceinline__ uint32_t bshr4(uint32_t v) {
    uint32_t t = (v >> 4) & 0x0F0F0F0Fu;
    return __vsub4(t ^ 0x08080808u, 0x08080808u);
}

// ---------------- GEMM config: BM=BN=128, BK=64 (int8), 3-stage ----------------
#define GBM 128
#define GBN 128
#define GBK 64
#define LROW 80                          // 64B + 16B pad: (r*5)%8 cycles all 16B banks
#define OFF_A1 0
#define OFF_A2 (GBM * LROW)              // 10240
#define OFF_B1 (2 * GBM * LROW)          // 20480
#define OFF_B2 (OFF_B1 + GBN * LROW)
#define STAGE  (OFF_B2 + GBN * LROW)     // 40960
#define NSTAGE 3
#define GSMEM  (NSTAGE * STAGE)          // 122880

__device__ __forceinline__ void cp_stage(
    uint32_t base, const uint8_t* __restrict__ A1, const uint8_t* __restrict__ A2,
    const uint8_t* __restrict__ B1, const uint8_t* __restrict__ B2,
    int rowBlock, int colBlock, int K, int kt, int t)
{
    #pragma unroll
    for (int i = 0; i < 2; i++) {                 // 512 16B chunks per tile
        int c = t + i * 256;
        int r = c >> 2, kc = (c & 3) * 16;
        uint32_t doff = (uint32_t)(r * LROW + kc);
        size_t ga = (size_t)(rowBlock + r) * K + kt + kc;
        size_t gb = (size_t)(colBlock + r) * K + kt + kc;
        CP16(base + OFF_A1 + doff, A1 + ga);
        CP16(base + OFF_A2 + doff, A2 + ga);
        CP16(base + OFF_B1 + doff, B1 + gb);
        CP16(base + OFF_B2 + doff, B2 + gb);
    }
}

// C = sA*sB*(P11 + (P12+P21)/256 + P22/65536);  A = sA(A1+A2/256), B likewise.
// EPI=1: phase-shift, write fp32 C0, track absmax -> maxOut.
// EPI=0: z picks (B1a/B2a, maxBa, C0) vs (B1b/B2b, maxBb, C1).
template<int EPI>
__global__ void __launch_bounds__(256, 1)
gemm_s8(const uint8_t* __restrict__ A1, const uint8_t* __restrict__ A2,
        const uint8_t* __restrict__ B1a, const uint8_t* __restrict__ B2a,
        const uint8_t* __restrict__ B1b, const uint8_t* __restrict__ B2b,
        float* __restrict__ C0, float* __restrict__ C1,
        int K, int N,
        const int* __restrict__ maxA, const int* __restrict__ maxBa,
        const int* __restrict__ maxBb, int* maxOut)
{
    extern __shared__ char smem_raw[];
    __shared__ float smax[8];
    const uint32_t sb = smem_u32(smem_raw);
    const int t = threadIdx.x, lane = t & 31, wid = t >> 5;
    const int wn = wid & 3, wm = wid >> 2;      // 2(M) x 4(N) warps; warp tile 64x32
    const int rowBlock = blockIdx.y * GBM;
    const int colBlock = blockIdx.x * GBN;

    const uint8_t* B1 = (EPI == 1 || blockIdx.z == 0) ? B1a : B1b;
    const uint8_t* B2 = (EPI == 1 || blockIdx.z == 0) ? B2a : B2b;
    const float mB = __int_as_float((EPI == 1 || blockIdx.z == 0) ? *maxBa : *maxBb);
    const float s1 = (__int_as_float(*maxA) / 127.f) * (mB / 127.f);
    const float s2 = s1 * (1.f / 256.f);

    int acc11[4][4][4], accX[4][4][4];
    #pragma unroll
    for (int mi = 0; mi < 4; mi++)
        #pragma unroll
        for (int ni = 0; ni < 4; ni++)
            #pragma unroll
            for (int e = 0; e < 4; e++) { acc11[mi][ni][e] = 0; accX[mi][ni][e] = 0; }

    const int NK = K / GBK;
    cp_stage(sb + 0 * STAGE, A1, A2, B1, B2, rowBlock, colBlock, K, 0, t);
    CP_COMMIT();
    cp_stage(sb + 1 * STAGE, A1, A2, B1, B2, rowBlock, colBlock, K, GBK, t);
    CP_COMMIT();

    const int a_row = (lane & 15), a_colB = ((lane >> 4) << 4);     // bytes
    const int b_row = (lane & 7),  b_colB = (((lane >> 3) & 1) << 4);

    int s_cur = 0, s_nxt = 2;
    for (int it = 0; it < NK; it++) {
        if (it < NK - 1) CP_WAIT1(); else CP_WAIT0();
        __syncthreads();

        const uint32_t base = sb + s_cur * STAGE;
        #pragma unroll
        for (int kk = 0; kk < GBK; kk += 32) {
            uint32_t b1[4][2], b2[4][2];
            #pragma unroll
            for (int ni = 0; ni < 4; ni++) {
                int row = wn * 32 + ni * 8 + b_row;
                uint32_t off = (uint32_t)(row * LROW + kk + b_colB);
                ldsm2(b1[ni], base + OFF_B1 + off);
                ldsm2(b2[ni], base + OFF_B2 + off);
            }
            uint32_t a1[4][4], a2[4][4];
            #pragma unroll
            for (int mi = 0; mi < 4; mi++) {
                int row = wm * 64 + mi * 16 + a_row;
                uint32_t off = (uint32_t)(row * LROW + kk + a_colB);
                ldsm4(a1[mi], base + OFF_A1 + off);
                ldsm4(a2[mi], base + OFF_A2 + off);
            }
            #pragma unroll
            for (int mi = 0; mi < 4; mi++)
                #pragma unroll
                for (int ni = 0; ni < 4; ni++) {
                    mma_s8(acc11[mi][ni], a1[mi], b1[ni]);
                    mma_s8(accX [mi][ni], a1[mi], b2[ni]);
                    mma_s8(accX [mi][ni], a2[mi], b1[ni]);
                }
            // P22/256 correction: shift both limb-2 fragments by >>4 in-place
            #pragma unroll
            for (int mi = 0; mi < 4; mi++)
                #pragma unroll
                for (int j = 0; j < 4; j++) a2[mi][j] = bshr4(a2[mi][j]);
            #pragma unroll
            for (int ni = 0; ni < 4; ni++) {
                b2[ni][0] = bshr4(b2[ni][0]);
                b2[ni][1] = bshr4(b2[ni][1]);
            }
            #pragma unroll
            for (int mi = 0; mi < 4; mi++)
                #pragma unroll
                for (int ni = 0; ni < 4; ni++)
                    mma_s8(accX[mi][ni], a2[mi], b2[ni]);
        }
        __syncthreads();

        if (it + 2 < NK) {
            cp_stage(sb + s_nxt * STAGE, A1, A2, B1, B2,
                     rowBlock, colBlock, K, (it + 2) * GBK, t);
            CP_COMMIT();
        }
        s_cur = (s_cur == NSTAGE - 1) ? 0 : s_cur + 1;
        s_nxt = (s_nxt == NSTAGE - 1) ? 0 : s_nxt + 1;
    }

    // ---------------- epilogue ----------------
    float tmax = 0.f;
    #pragma unroll
    for (int mi = 0; mi < 4; mi++) {
        #pragma unroll
        for (int ni = 0; ni < 4; ni++) {
            float v0 = s1 * (float)acc11[mi][ni][0] + s2 * (float)accX[mi][ni][0];
            float v1 = s1 * (float)acc11[mi][ni][1] + s2 * (float)accX[mi][ni][1];
            float v2 = s1 * (float)acc11[mi][ni][2] + s2 * (float)accX[mi][ni][2];
            float v3 = s1 * (float)acc11[mi][ni][3] + s2 * (float)accX[mi][ni][3];
            int r0 = rowBlock + wm * 64 + mi * 16 + (lane >> 2);
            int r1 = r0 + 8;
            int c  = colBlock + wn * 32 + ni * 8 + (lane & 3) * 2;
            if (EPI == 1) {
                int o = c & 511;
                if (o == 0) {
                    int ci = c >> 9;
                    float ph = 6.28318530717958647692f * (float)ci / 7.0f;
                    v0 *= cosf(ph); v1 *= sinf(ph);
                    v2 *= cosf(ph); v3 *= sinf(ph);
                }
                tmax = fmaxf(tmax, fmaxf(fmaxf(fabsf(v0), fabsf(v1)),
                                         fmaxf(fabsf(v2), fabsf(v3))));
                *(float2*)(C0 + (size_t)r0 * N + c) = make_float2(v0, v1);
                *(float2*)(C0 + (size_t)r1 * N + c) = make_float2(v2, v3);
            } else {
                float* Cf = (blockIdx.z == 0) ? C0 : C1;
                *(float2*)(Cf + (size_t)r0 * N + c) = make_float2(v0, v1);
                *(float2*)(Cf + (size_t)r1 * N + c) = make_float2(v2, v3);
            }
        }
    }
    if (EPI == 1) {
        #pragma unroll
        for (int o = 16; o; o >>= 1) tmax = fmaxf(tmax, __shfl_xor_sync(0xffffffffu, tmax, o));
        if (lane == 0) smax[wid] = tmax;
        __syncthreads();
        if (t == 0) {
            float m = smax[0];
            #pragma unroll
            for (int i = 1; i < 8; i++) m = fmaxf(m, smax[i]);
            atomicMax(maxOut, __float_as_int(m));
        }
    }
}

// ---------------- elementwise kernels ----------------
__device__ __forceinline__ float blockReduceSum(float v) {
    __shared__ float sh[33];
    int lane = threadIdx.x & 31, wid = threadIdx.x >> 5;
    #pragma unroll
    for (int o = 16; o; o >>= 1) v += __shfl_down_sync(0xffffffffu, v, o);
    if (lane == 0) sh[wid] = v;
    __syncthreads();
    if (wid == 0) {
        v = (threadIdx.x < (blockDim.x >> 5)) ? sh[lane] : 0.f;
        #pragma unroll
        for (int o = 16; o; o >>= 1) v += __shfl_down_sync(0xffffffffu, v, o);
        if (lane == 0) sh[32] = v;
    }
    __syncthreads();
    return sh[32];
}

__global__ void k_init() {
    g_mx = 0; g_mwf = 0; g_mwm = 0; g_mwe = 0; g_mxe = 0;
}

__global__ void __launch_bounds__(256) k_scale(const float* __restrict__ x) {
    int b  = blockIdx.x;
    int bp = (b == 0) ? (BROWS - 1) : (b - 1);
    const float4* r0 = (const float4*)(x + (size_t)b  * DIN);
    const float4* r1 = (const float4*)(x + (size_t)bp * DIN);
    float ss = 0.f;
    for (int i = threadIdx.x; i < DIN / 4; i += 256) {
        float4 a = r0[i], c = r1[i];
        float dx = a.x - c.x, dy = a.y - c.y, dz = a.z - c.z, dw = a.w - c.w;
        ss += dx*dx + dy*dy + dz*dz + dw*dw;
    }
    ss = blockReduceSum(ss);
    if (threadIdx.x == 0) {
        float dist = sqrtf(ss);
        g_scale[b] = 1.f + fmaxf(0.f, 1.f - fabsf(dist - 1.f));
    }
}

__device__ __forceinline__ void blockAtomicMax(float v, int* target) {
    __shared__ float sm[8];
    int lane = threadIdx.x & 31, wid = threadIdx.x >> 5;
    #pragma unroll
    for (int o = 16; o; o >>= 1) v = fmaxf(v, __shfl_xor_sync(0xffffffffu, v, o));
    if (lane == 0) sm[wid] = v;
    __syncthreads();
    if (threadIdx.x == 0) {
        float m = sm[0];
        for (int i = 1; i < (int)(blockDim.x >> 5); i++) m = fmaxf(m, sm[i]);
        atomicMax(target, __float_as_int(m));
    }
}

__global__ void __launch_bounds__(256) k_absmax_x(const float* __restrict__ x, int* target) {
    float m = 0.f;
    for (size_t i = (size_t)blockIdx.x * 256 + threadIdx.x;
         i < (size_t)BROWS * DIN / 4; i += (size_t)gridDim.x * 256) {
        float s = g_scale[i / (DIN / 4)];
        float4 v = ((const float4*)x)[i];
        m = fmaxf(m, fmaxf(fmaxf(fabsf(v.x), fabsf(v.y)), fmaxf(fabsf(v.z), fabsf(v.w))) * s);
    }
    blockAtomicMax(m, target);
}

__global__ void __launch_bounds__(256) k_absmax(const float* __restrict__ p, size_t n4, int* target) {
    float m = 0.f;
    for (size_t i = (size_t)blockIdx.x * 256 + threadIdx.x; i < n4; i += (size_t)gridDim.x * 256) {
        float4 v = ((const float4*)p)[i];
        m = fmaxf(m, fmaxf(fmaxf(fabsf(v.x), fabsf(v.y)), fmaxf(fabsf(v.z), fabsf(v.w))));
    }
    blockAtomicMax(m, target);
}

__device__ __forceinline__ void q2(float v, float inv, float s, int& q1, int& q2r) {
    float a1 = fminf(fmaxf(rintf(v * inv), -127.f), 127.f);
    float r  = v - a1 * s;
    float a2 = fminf(fmaxf(rintf(r * inv * 256.f), -127.f), 127.f);
    q1 = (int)a1; q2r = (int)a2;
}
__device__ __forceinline__ uint32_t pack4(int a, int b, int c, int d) {
    return (uint32_t)(a & 0xFF) | ((uint32_t)(b & 0xFF) << 8) |
           ((uint32_t)(c & 0xFF) << 16) | ((uint32_t)(d & 0xFF) << 24);
}
__device__ __forceinline__ void quant_store4(float4 v, float inv, float s,
                                             uint8_t* q1p, uint8_t* q2p, size_t i4) {
    int a1, a2, b1, b2, c1, c2, d1, d2;
    q2(v.x, inv, s, a1, a2); q2(v.y, inv, s, b1, b2);
    q2(v.z, inv, s, c1, c2); q2(v.w, inv, s, d1, d2);
    ((uint32_t*)q1p)[i4] = pack4(a1, b1, c1, d1);
    ((uint32_t*)q2p)[i4] = pack4(a2, b2, c2, d2);
}

__global__ void __launch_bounds__(256) k_quant_x(const float* __restrict__ x) {
    size_t i = (size_t)blockIdx.x * 256 + threadIdx.x;
    if (i >= (size_t)BROWS * DIN / 4) return;
    float mx = __int_as_float(g_mx);
    float s = mx / 127.f, inv = 127.f / mx;
    float rs = g_scale[i / (DIN / 4)];
    float4 v = ((const float4*)x)[i];
    v.x *= rs; v.y *= rs; v.z *= rs; v.w *= rs;
    quant_store4(v, inv, s, g_qx1, g_qx2, i);
}

__global__ void __launch_bounds__(256) k_quant(const float* __restrict__ src, size_t n4,
                                               uint8_t* __restrict__ q1p, uint8_t* __restrict__ q2p,
                                               const int* __restrict__ mptr) {
    size_t i = (size_t)blockIdx.x * 256 + threadIdx.x;
    if (i >= n4) return;
    float mx = __int_as_float(*mptr);
    float s = mx / 127.f, inv = 127.f / mx;
    quant_store4(((const float4*)src)[i], inv, s, q1p, q2p, i);
}

__global__ void __launch_bounds__(256) k_quant_flip(const float* __restrict__ src) {
    size_t i = (size_t)blockIdx.x * 256 + threadIdx.x;   // float4 idx over [DOUT, DHID]
    if (i >= (size_t)DOUT * DHID / 4) return;
    float mx = __int_as_float(g_mwe);
    float s = mx / 127.f, inv = 127.f / mx;
    int o  = (int)(i / (DHID / 4));
    int h4 = (int)(i % (DHID / 4)) * 4;
    float4 v = *(const float4*)(src + (size_t)o * DHID + (DHID - 4 - h4));
    float4 rv = make_float4(v.w, v.z, v.y, v.x);
    quant_store4(rv, inv, s, g_qwe1, g_qwe2, i);
}

__global__ void __launch_bounds__(256) k_quant_xe() {
    size_t i = (size_t)blockIdx.x * 256 + threadIdx.x;
    if (i >= (size_t)BROWS * DHID / 4) return;
    float mx = __int_as_float(g_mxe);
    float s = mx / 127.f, inv = 127.f / mx;
    quant_store4(((const float4*)g_xef)[i], inv, s, g_qxe1, g_qxe2, i);
}

__global__ void __launch_bounds__(256) k_final(float* __restrict__ out) {
    int b = blockIdx.x;
    const float4* mr = (const float4*)(g_male + (size_t)b * DOUT);
    const float4* fr = (const float4*)(g_fem  + (size_t)b * DOUT);
    int i0 = threadIdx.x, i1 = threadIdx.x + 256;
    float4 m0 = mr[i0], m1 = mr[i1];
    float4 f0 = fr[i0], f1 = fr[i1];
    float s = m0.x*f0.x + m0.y*f0.y + m0.z*f0.z + m0.w*f0.w
            + m1.x*f1.x + m1.y*f1.y + m1.z*f1.z + m1.w*f1.w;
    s = blockReduceSum(s);
    float pl = 1.f / (1.f + expf(-s));
    float om = 1.f - pl;
    float4* o4 = (float4*)(out + (size_t)b * DOUT);
    o4[i0] = make_float4(pl*m0.x + om*f0.x, pl*m0.y + om*f0.y,
                         pl*m0.z + om*f0.z, pl*m0.w + om*f0.w);
    o4[i1] = make_float4(pl*m1.x + om*f1.x, pl*m1.y + om*f1.y,
                         pl*m1.z + om*f1.z, pl*m1.w + om*f1.w);
}

// ---------------- launch ----------------
extern "C" void kernel_launch(void* const* d_in, const int* in_sizes, int n_in,
                              void* d_out, int out_size) {
    const float* x   = (const float*)d_in[0];   // [4096, 2048]
    const float* wfl = (const float*)d_in[1];   // [3584, 2048]
    const float* wm  = (const float*)d_in[2];   // [2048, 3584]
    const float* wfe = (const float*)d_in[3];   // [2048, 3584]
    float* out = (float*)d_out;

    uint8_t *qx1,*qx2,*qwf1,*qwf2,*qwm1,*qwm2,*qwe1,*qwe2,*qxe1,*qxe2;
    float *xef,*male,*fem;
    int *mx,*mwf,*mwm,*mwe,*mxe;
    cudaGetSymbolAddress((void**)&qx1,  g_qx1);  cudaGetSymbolAddress((void**)&qx2,  g_qx2);
    cudaGetSymbolAddress((void**)&qwf1, g_qwf1); cudaGetSymbolAddress((void**)&qwf2, g_qwf2);
    cudaGetSymbolAddress((void**)&qwm1, g_qwm1); cudaGetSymbolAddress((void**)&qwm2, g_qwm2);
    cudaGetSymbolAddress((void**)&qwe1, g_qwe1); cudaGetSymbolAddress((void**)&qwe2, g_qwe2);
    cudaGetSymbolAddress((void**)&qxe1, g_qxe1); cudaGetSymbolAddress((void**)&qxe2, g_qxe2);
    cudaGetSymbolAddress((void**)&xef,  g_xef);
    cudaGetSymbolAddress((void**)&male, g_male); cudaGetSymbolAddress((void**)&fem,  g_fem);
    cudaGetSymbolAddress((void**)&mx,  g_mx);  cudaGetSymbolAddress((void**)&mwf, g_mwf);
    cudaGetSymbolAddress((void**)&mwm, g_mwm); cudaGetSymbolAddress((void**)&mwe, g_mwe);
    cudaGetSymbolAddress((void**)&mxe, g_mxe);

    cudaFuncSetAttribute(gemm_s8<1>, cudaFuncAttributeMaxDynamicSharedMemorySize, GSMEM);
    cudaFuncSetAttribute(gemm_s8<0>, cudaFuncAttributeMaxDynamicSharedMemorySize, GSMEM);

    const size_t nX  = (size_t)BROWS * DIN  / 4;
    const size_t nWF = (size_t)DHID  * DIN  / 4;
    const size_t nWM = (size_t)DOUT  * DHID / 4;
    const size_t nXE = (size_t)BROWS * DHID / 4;

    // 0) reset maxes (must be deterministic per call)
    k_init<<<1, 1>>>();
    // 1) vesica row scales + absmax reductions
    k_scale<<<BROWS, 256>>>(x);
    k_absmax_x<<<1024, 256>>>(x, mx);
    k_absmax<<<1024, 256>>>(wfl, nWF, mwf);
    k_absmax<<<1024, 256>>>(wm,  nWM, mwm);
    k_absmax<<<1024, 256>>>(wfe, nWM, mwe);
    // 2) quantize inputs
    k_quant_x<<<(unsigned)((nX + 255) / 256), 256>>>(x);
    k_quant<<<(unsigned)((nWF + 255) / 256), 256>>>(wfl, nWF, qwf1, qwf2, mwf);
    k_quant<<<(unsigned)((nWM + 255) / 256), 256>>>(wm,  nWM, qwm1, qwm2, mwm);
    k_quant_flip<<<(unsigned)((nWM + 255) / 256), 256>>>(wfe);
    // 3) GEMM1: x_expanded (fp32 + absmax), phase epilogue
    {
        dim3 grid(DHID / GBN, BROWS / GBM, 1);
        gemm_s8<1><<<grid, 256, GSMEM>>>(qx1, qx2, qwf1, qwf2, qwf1, qwf2,
                                         xef, xef, DIN, DHID, mx, mwf, mwf, mxe);
    }
    // 4) quantize x_expanded
    k_quant_xe<<<(unsigned)((nXE + 255) / 256), 256>>>();
    // 5) GEMM2: male (z=0) / female (z=1)
    {
        dim3 grid(DOUT / GBN, BROWS / GBM, 2);
        gemm_s8<0><<<grid, 256, GSMEM>>>(qxe1, qxe2, qwm1, qwm2, qwe1, qwe2,
                                         male, fem, DHID, DOUT, mxe, mwm, mwe, nullptr);
    }
    // 6) phase-lock blend
    k_final<<<BROWS, 256>>>(out);
}

// round 10
// speedup vs baseline: 3.4598x; 3.4598x over previous
#include <cuda_runtime.h>
#include <cuda_fp16.h>
#include <cstdint>
#include <math.h>

#define BROWS 4096
#define DIN   2048
#define DHID  3584
#define DOUT  2048

// ---------------- scratch (static __device__, no allocation) ----------------
__device__ __align__(16) __half g_xh  [(size_t)BROWS*DIN];
__device__ __align__(16) __half g_xl  [(size_t)BROWS*DIN];
__device__ __align__(16) __half g_wflh[(size_t)DHID*DIN];
__device__ __align__(16) __half g_wfll[(size_t)DHID*DIN];
__device__ __align__(16) __half g_wmh [(size_t)DOUT*DHID];
__device__ __align__(16) __half g_wml [(size_t)DOUT*DHID];
__device__ __align__(16) __half g_wfh [(size_t)DOUT*DHID];   // flipped female hi
__device__ __align__(16) __half g_wfl2[(size_t)DOUT*DHID];   // flipped female lo
__device__ __align__(16) __half g_xeh [(size_t)BROWS*DHID];
__device__ __align__(16) __half g_xel [(size_t)BROWS*DHID];
__device__ __align__(16) float  g_male[(size_t)BROWS*DOUT];
__device__ __align__(16) float  g_fem [(size_t)BROWS*DOUT];

// ---------------- PTX helpers (generic sm_80-era, legal on compute_103) ----
__device__ __forceinline__ uint32_t smem_u32(const void* p) {
    uint32_t a;
    asm("{ .reg .u64 t; cvta.to.shared.u64 t, %1; cvt.u32.u64 %0, t; }" : "=r"(a) : "l"(p));
    return a;
}
#define CP16(dst, src) asm volatile("cp.async.cg.shared.global [%0], [%1], 16;" :: "r"(dst), "l"(src))
#define CP_COMMIT()    asm volatile("cp.async.commit_group;" ::: "memory")
#define CP_WAIT1()     asm volatile("cp.async.wait_group 1;" ::: "memory")
#define CP_WAIT0()     asm volatile("cp.async.wait_group 0;" ::: "memory")

__device__ __forceinline__ void ldsm4(uint32_t* r, uint32_t addr) {
    asm volatile("ldmatrix.sync.aligned.m8n8.x4.shared.b16 {%0,%1,%2,%3}, [%4];"
                 : "=r"(r[0]), "=r"(r[1]), "=r"(r[2]), "=r"(r[3]) : "r"(addr));
}
__device__ __forceinline__ void ldsm2(uint32_t* r, uint32_t addr) {
    asm volatile("ldmatrix.sync.aligned.m8n8.x2.shared.b16 {%0,%1}, [%2];"
                 : "=r"(r[0]), "=r"(r[1]) : "r"(addr));
}
__device__ __forceinline__ void mma16816(float* c, const uint32_t* a, const uint32_t* b) {
    asm volatile(
        "mma.sync.aligned.m16n8k16.row.col.f32.f16.f16.f32 "
        "{%0,%1,%2,%3}, {%4,%5,%6,%7}, {%8,%9}, {%0,%1,%2,%3};"
        : "+f"(c[0]), "+f"(c[1]), "+f"(c[2]), "+f"(c[3])
        : "r"(a[0]), "r"(a[1]), "r"(a[2]), "r"(a[3]), "r"(b[0]), "r"(b[1]));
}

// ---------------- GEMM config: BM=BN=128, BK=64 (fp16), 2-stage ----------------
#define GBM 128
#define GBN 128
#define GBK 64
#define LROW 72                          // 64 + 8 halfs pad (144B stride: 8 rows cycle all 16B banks)
#define TILE_B (GBM * LROW * 2)          // 18432 B per tile
#define OFF_AH 0
#define OFF_AL TILE_B
#define OFF_BH (2 * TILE_B)
#define OFF_BL (3 * TILE_B)
#define STAGE  (4 * TILE_B)              // 73728 B
#define GSMEM  (2 * STAGE)               // 147456 B
#define INV2048 4.8828125e-4f

__device__ __forceinline__ void cp_stage(
    uint32_t base, const __half* __restrict__ Ah, const __half* __restrict__ Al,
    const __half* __restrict__ Bh, const __half* __restrict__ Bl,
    int rowBlock, int colBlock, int K, int kt, int t)
{
    // each tile: 128 rows x 8 chunks(16B) = 1024 chunks; 4 per thread per tile
    #pragma unroll
    for (int i = 0; i < 4; i++) {
        int c = t + i * 256;
        int r = c >> 3, kc = (c & 7) * 8;               // kc in halves
        uint32_t doff = (uint32_t)((r * LROW + kc) * 2);
        size_t ga = (size_t)(rowBlock + r) * K + kt + kc;
        size_t gb = (size_t)(colBlock + r) * K + kt + kc;
        CP16(base + OFF_AH + doff, Ah + ga);
        CP16(base + OFF_AL + doff, Al + ga);
        CP16(base + OFF_BH + doff, Bh + gb);
        CP16(base + OFF_BL + doff, Bl + gb);
    }
}

// C = (Ah + Al/2048) @ (Bh + Bl/2048)^T, al*bl dropped.
// EPI=1: phase-shift epilogue, split-write half C0(hi)/C1(lo*2048).
// EPI=0: z selects weights/outputs; float write.
template<int EPI>
__global__ void __launch_bounds__(256, 1)
gemm_fp16x3(const __half* __restrict__ Ah, const __half* __restrict__ Al,
            const __half* __restrict__ Bh0, const __half* __restrict__ Bl0,
            const __half* __restrict__ Bh1, const __half* __restrict__ Bl1,
            void* __restrict__ C0v, void* __restrict__ C1v,
            int K, int N)
{
    extern __shared__ char smem_raw[];
    const uint32_t sb = smem_u32(smem_raw);
    const int t = threadIdx.x, lane = t & 31, wid = t >> 5;
    const int wn = wid & 3, wm = wid >> 2;     // 2(M) x 4(N) warps; warp tile 64x32
    const int rowBlock = blockIdx.y * GBM;
    const int colBlock = blockIdx.x * GBN;

    const __half* Bh = (EPI == 1 || blockIdx.z == 0) ? Bh0 : Bh1;
    const __half* Bl = (EPI == 1 || blockIdx.z == 0) ? Bl0 : Bl1;

    float acc_hh[4][4][4];
    float acc_x [4][4][4];
    #pragma unroll
    for (int mi = 0; mi < 4; mi++)
        #pragma unroll
        for (int ni = 0; ni < 4; ni++)
            #pragma unroll
            for (int e = 0; e < 4; e++) { acc_hh[mi][ni][e] = 0.f; acc_x[mi][ni][e] = 0.f; }

    const int NK = K / GBK;
    cp_stage(sb, Ah, Al, Bh, Bl, rowBlock, colBlock, K, 0, t);
    CP_COMMIT();

    const int a_row = (lane & 15), a_col = ((lane >> 4) << 3);
    const int b_row = (lane & 7),  b_col = (((lane >> 3) & 1) << 3);

    for (int it = 0; it < NK; it++) {
        if (it + 1 < NK) {
            cp_stage(sb + ((it + 1) & 1) * STAGE, Ah, Al, Bh, Bl,
                     rowBlock, colBlock, K, (it + 1) * GBK, t);
            CP_COMMIT();
            CP_WAIT1();
        } else {
            CP_WAIT0();
        }
        __syncthreads();

        const uint32_t base = sb + (it & 1) * STAGE;
        #pragma unroll
        for (int kk = 0; kk < GBK; kk += 16) {
            uint32_t b_h[4][2], b_l[4][2];
            #pragma unroll
            for (int ni = 0; ni < 4; ni++) {
                int row = wn * 32 + ni * 8 + b_row;
                uint32_t off = (uint32_t)((row * LROW + kk + b_col) * 2);
                ldsm2(b_h[ni], base + OFF_BH + off);
                ldsm2(b_l[ni], base + OFF_BL + off);
            }
            uint32_t a_h[4][4], a_l[4][4];
            #pragma unroll
            for (int mi = 0; mi < 4; mi++) {
                int row = wm * 64 + mi * 16 + a_row;
                uint32_t off = (uint32_t)((row * LROW + kk + a_col) * 2);
                ldsm4(a_h[mi], base + OFF_AH + off);
                ldsm4(a_l[mi], base + OFF_AL + off);
            }
            // term-grouped issue: 16 independent mma between writes to same acc
            #pragma unroll
            for (int mi = 0; mi < 4; mi++)
                #pragma unroll
                for (int ni = 0; ni < 4; ni++)
                    mma16816(acc_hh[mi][ni], a_h[mi], b_h[ni]);
            #pragma unroll
            for (int mi = 0; mi < 4; mi++)
                #pragma unroll
                for (int ni = 0; ni < 4; ni++)
                    mma16816(acc_x[mi][ni], a_h[mi], b_l[ni]);
            #pragma unroll
            for (int mi = 0; mi < 4; mi++)
                #pragma unroll
                for (int ni = 0; ni < 4; ni++)
                    mma16816(acc_x[mi][ni], a_l[mi], b_h[ni]);
        }
        __syncthreads();
    }

    // ---------------- epilogue ----------------
    #pragma unroll
    for (int mi = 0; mi < 4; mi++) {
        #pragma unroll
        for (int ni = 0; ni < 4; ni++) {
            float v0 = acc_hh[mi][ni][0] + acc_x[mi][ni][0] * INV2048;
            float v1 = acc_hh[mi][ni][1] + acc_x[mi][ni][1] * INV2048;
            float v2 = acc_hh[mi][ni][2] + acc_x[mi][ni][2] * INV2048;
            float v3 = acc_hh[mi][ni][3] + acc_x[mi][ni][3] * INV2048;
            int r0 = rowBlock + wm * 64 + mi * 16 + (lane >> 2);
            int r1 = r0 + 8;
            int c  = colBlock + wn * 32 + ni * 8 + (lane & 3) * 2;
            if (EPI == 1) {
                int o = c & 511;
                if (o == 0) {
                    int ci = c >> 9;
                    float ph = 6.28318530717958647692f * (float)ci / 7.0f;
                    float p0 = cosf(ph), p1 = sinf(ph);
                    v0 *= p0; v1 *= p1; v2 *= p0; v3 *= p1;
                }
                __half* Ch = (__half*)C0v;
                __half* Cl = (__half*)C1v;
                __half h0 = __float2half_rn(v0), h1 = __float2half_rn(v1);
                __half h2 = __float2half_rn(v2), h3 = __float2half_rn(v3);
                __half l0 = __float2half_rn((v0 - __half2float(h0)) * 2048.f);
                __half l1 = __float2half_rn((v1 - __half2float(h1)) * 2048.f);
                __half l2 = __float2half_rn((v2 - __half2float(h2)) * 2048.f);
                __half l3 = __float2half_rn((v3 - __half2float(h3)) * 2048.f);
                *(__half2*)(Ch + (size_t)r0 * N + c) = __halves2half2(h0, h1);
                *(__half2*)(Ch + (size_t)r1 * N + c) = __halves2half2(h2, h3);
                *(__half2*)(Cl + (size_t)r0 * N + c) = __halves2half2(l0, l1);
                *(__half2*)(Cl + (size_t)r1 * N + c) = __halves2half2(l2, l3);
            } else {
                float* Cf = (blockIdx.z == 0) ? (float*)C0v : (float*)C1v;
                *(float2*)(Cf + (size_t)r0 * N + c) = make_float2(v0, v1);
                *(float2*)(Cf + (size_t)r1 * N + c) = make_float2(v2, v3);
            }
        }
    }
}

// ---------------- elementwise kernels ----------------
__device__ __forceinline__ float blockReduceSum(float v) {
    __shared__ float sh[33];
    int lane = threadIdx.x & 31, wid = threadIdx.x >> 5;
    #pragma unroll
    for (int o = 16; o; o >>= 1) v += __shfl_down_sync(0xffffffffu, v, o);
    if (lane == 0) sh[wid] = v;
    __syncthreads();
    if (wid == 0) {
        v = (threadIdx.x < (blockDim.x >> 5)) ? sh[lane] : 0.f;
        #pragma unroll
        for (int o = 16; o; o >>= 1) v += __shfl_down_sync(0xffffffffu, v, o);
        if (lane == 0) sh[32] = v;
    }
    __syncthreads();
    return sh[32];
}

__device__ __forceinline__ void split_store(__half* hi, __half* lo, size_t idx2, float a, float b) {
    __half ha = __float2half_rn(a), hb = __float2half_rn(b);
    __half la = __float2half_rn((a - __half2float(ha)) * 2048.f);
    __half lb = __float2half_rn((b - __half2float(hb)) * 2048.f);
    ((__half2*)hi)[idx2] = __halves2half2(ha, hb);
    ((__half2*)lo)[idx2] = __halves2half2(la, lb);
}

// fused: vesica row scale + scaled split of x
__global__ void __launch_bounds__(256) k_scale_split(const float* __restrict__ x) {
    int b  = blockIdx.x;
    int bp = (b == 0) ? (BROWS - 1) : (b - 1);
    const float4* r0 = (const float4*)(x + (size_t)b  * DIN);
    const float4* r1 = (const float4*)(x + (size_t)bp * DIN);
    float ss = 0.f;
    float4 va[2];
    #pragma unroll
    for (int j = 0; j < 2; j++) {
        int i = threadIdx.x + j * 256;
        float4 a = r0[i], c = r1[i];
        va[j] = a;
        float dx = a.x - c.x, dy = a.y - c.y, dz = a.z - c.z, dw = a.w - c.w;
        ss += dx*dx + dy*dy + dz*dz + dw*dw;
    }
    ss = blockReduceSum(ss);          // broadcast
    float dist = sqrtf(ss);
    float s = 1.f + fmaxf(0.f, 1.f - fabsf(dist - 1.f));
    size_t rowBase = (size_t)b * (DIN / 4);
    #pragma unroll
    for (int j = 0; j < 2; j++) {
        size_t i4 = rowBase + threadIdx.x + j * 256;
        split_store(g_xh, g_xl, i4 * 2 + 0, va[j].x * s, va[j].y * s);
        split_store(g_xh, g_xl, i4 * 2 + 1, va[j].z * s, va[j].w * s);
    }
}

__global__ void __launch_bounds__(256) k_split(const float* __restrict__ src,
                                               __half* __restrict__ hi, __half* __restrict__ lo,
                                               size_t n4) {
    size_t i = (size_t)blockIdx.x * 256 + threadIdx.x;
    if (i >= n4) return;
    float4 v = ((const float4*)src)[i];
    split_store(hi, lo, i * 2 + 0, v.x, v.y);
    split_store(hi, lo, i * 2 + 1, v.z, v.w);
}

__global__ void __launch_bounds__(256) k_split_flip(const float* __restrict__ src,
                                                    __half* __restrict__ hi, __half* __restrict__ lo) {
    size_t i = (size_t)blockIdx.x * 256 + threadIdx.x;   // float4 index over [DOUT, DHID]
    if (i >= (size_t)DOUT * DHID / 4) return;
    int o  = (int)(i / (DHID / 4));
    int h4 = (int)(i % (DHID / 4)) * 4;
    float4 v = *(const float4*)(src + (size_t)o * DHID + (DHID - 4 - h4));
    split_store(hi, lo, i * 2 + 0, v.w, v.z);
    split_store(hi, lo, i * 2 + 1, v.y, v.x);
}

__global__ void __launch_bounds__(256) k_final(float* __restrict__ out) {
    int b = blockIdx.x;
    const float4* mr = (const float4*)(g_male + (size_t)b * DOUT);
    const float4* fr = (const float4*)(g_fem  + (size_t)b * DOUT);
    int i0 = threadIdx.x, i1 = threadIdx.x + 256;
    float4 m0 = mr[i0], m1 = mr[i1];
    float4 f0 = fr[i0], f1 = fr[i1];
    float s = m0.x*f0.x + m0.y*f0.y + m0.z*f0.z + m0.w*f0.w
            + m1.x*f1.x + m1.y*f1.y + m1.z*f1.z + m1.w*f1.w;
    s = blockReduceSum(s);
    float pl = 1.f / (1.f + expf(-s));
    float om = 1.f - pl;
    float4* o4 = (float4*)(out + (size_t)b * DOUT);
    o4[i0] = make_float4(pl*m0.x + om*f0.x, pl*m0.y + om*f0.y,
                         pl*m0.z + om*f0.z, pl*m0.w + om*f0.w);
    o4[i1] = make_float4(pl*m1.x + om*f1.x, pl*m1.y + om*f1.y,
                         pl*m1.z + om*f1.z, pl*m1.w + om*f1.w);
}

// ---------------- launch ----------------
extern "C" void kernel_launch(void* const* d_in, const int* in_sizes, int n_in,
                              void* d_out, int out_size) {
    const float* x   = (const float*)d_in[0];   // [4096, 2048]
    const float* wfl = (const float*)d_in[1];   // [3584, 2048]
    const float* wm  = (const float*)d_in[2];   // [2048, 3584]
    const float* wfe = (const float*)d_in[3];   // [2048, 3584]
    float* out = (float*)d_out;

    __half *xh, *xl, *wflh, *wfll, *wmh, *wml, *wfh, *wfl2, *xeh, *xel;
    float *male, *fem;
    cudaGetSymbolAddress((void**)&xh,   g_xh);
    cudaGetSymbolAddress((void**)&xl,   g_xl);
    cudaGetSymbolAddress((void**)&wflh, g_wflh);
    cudaGetSymbolAddress((void**)&wfll, g_wfll);
    cudaGetSymbolAddress((void**)&wmh,  g_wmh);
    cudaGetSymbolAddress((void**)&wml,  g_wml);
    cudaGetSymbolAddress((void**)&wfh,  g_wfh);
    cudaGetSymbolAddress((void**)&wfl2, g_wfl2);
    cudaGetSymbolAddress((void**)&xeh,  g_xeh);
    cudaGetSymbolAddress((void**)&xel,  g_xel);
    cudaGetSymbolAddress((void**)&male, g_male);
    cudaGetSymbolAddress((void**)&fem,  g_fem);

    cudaFuncSetAttribute(gemm_fp16x3<1>, cudaFuncAttributeMaxDynamicSharedMemorySize, GSMEM);
    cudaFuncSetAttribute(gemm_fp16x3<0>, cudaFuncAttributeMaxDynamicSharedMemorySize, GSMEM);

    // 1) vesica scale + x split (fused) and weight splits
    k_scale_split<<<BROWS, 256>>>(x);
    k_split<<<(unsigned)(((size_t)DHID * DIN / 4 + 255) / 256), 256>>>(wfl, wflh, wfll, (size_t)DHID * DIN / 4);
    k_split<<<(unsigned)(((size_t)DOUT * DHID / 4 + 255) / 256), 256>>>(wm, wmh, wml, (size_t)DOUT * DHID / 4);
    k_split_flip<<<(unsigned)(((size_t)DOUT * DHID / 4 + 255) / 256), 256>>>(wfe, wfh, wfl2);

    // 2) GEMM1: x_expanded (phase epilogue + fp16 split write) = x_overlap @ W_flower^T
    {
        dim3 grid(DHID / GBN, BROWS / GBM, 1);
        gemm_fp16x3<1><<<grid, 256, GSMEM>>>(xh, xl, wflh, wfll, wflh, wfll,
                                             xeh, xel, DIN, DHID);
    }

    // 3) GEMM2 (z=0 male / z=1 female): xexp @ W^T
    {
        dim3 grid(DOUT / GBN, BROWS / GBM, 2);
        gemm_fp16x3<0><<<grid, 256, GSMEM>>>(xeh, xel, wmh, wml, wfh, wfl2,
                                             male, fem, DHID, DOUT);
    }

    // 4) phase-lock blend
    k_final<<<BROWS, 256>>>(out);
}

// round 11
// speedup vs baseline: 3.8077x; 1.1005x over previous
#include <cuda_runtime.h>
#include <cuda_fp16.h>
#include <cstdint>
#include <math.h>

#define BROWS 4096
#define DIN   2048
#define DHID  3584
#define DOUT  2048

// ---------------- scratch (static __device__, no allocation) ----------------
__device__ __align__(16) __half g_xh  [(size_t)BROWS*DIN];
__device__ __align__(16) __half g_xl  [(size_t)BROWS*DIN];   // kept (unused by GEMM1 now)
__device__ __align__(16) __half g_wflh[(size_t)DHID*DIN];
__device__ __align__(16) __half g_wfll[(size_t)DHID*DIN];
__device__ __align__(16) __half g_wmh [(size_t)DOUT*DHID];
__device__ __align__(16) __half g_wml [(size_t)DOUT*DHID];
__device__ __align__(16) __half g_wfh [(size_t)DOUT*DHID];   // flipped female hi
__device__ __align__(16) __half g_wfl2[(size_t)DOUT*DHID];   // flipped female lo
__device__ __align__(16) __half g_xeh [(size_t)BROWS*DHID];
__device__ __align__(16) __half g_xel [(size_t)BROWS*DHID];
__device__ __align__(16) float  g_male[(size_t)BROWS*DOUT];
__device__ __align__(16) float  g_fem [(size_t)BROWS*DOUT];

// ---------------- PTX helpers (generic sm_80-era, legal on compute_103) ----
__device__ __forceinline__ uint32_t smem_u32(const void* p) {
    uint32_t a;
    asm("{ .reg .u64 t; cvta.to.shared.u64 t, %1; cvt.u32.u64 %0, t; }" : "=r"(a) : "l"(p));
    return a;
}
#define CP16(dst, src) asm volatile("cp.async.cg.shared.global [%0], [%1], 16;" :: "r"(dst), "l"(src))
#define CP_COMMIT()    asm volatile("cp.async.commit_group;" ::: "memory")
#define CP_WAIT1()     asm volatile("cp.async.wait_group 1;" ::: "memory")
#define CP_WAIT0()     asm volatile("cp.async.wait_group 0;" ::: "memory")

__device__ __forceinline__ void ldsm4(uint32_t* r, uint32_t addr) {
    asm volatile("ldmatrix.sync.aligned.m8n8.x4.shared.b16 {%0,%1,%2,%3}, [%4];"
                 : "=r"(r[0]), "=r"(r[1]), "=r"(r[2]), "=r"(r[3]) : "r"(addr));
}
__device__ __forceinline__ void mma16816(float* c, const uint32_t* a, const uint32_t* b) {
    asm volatile(
        "mma.sync.aligned.m16n8k16.row.col.f32.f16.f16.f32 "
        "{%0,%1,%2,%3}, {%4,%5,%6,%7}, {%8,%9}, {%0,%1,%2,%3};"
        : "+f"(c[0]), "+f"(c[1]), "+f"(c[2]), "+f"(c[3])
        : "r"(a[0]), "r"(a[1]), "r"(a[2]), "r"(a[3]), "r"(b[0]), "r"(b[1]));
}

// ---------------- GEMM config: BM=BN=128, BK=64 (fp16), 2-stage ----------------
#define GBM 128
#define GBN 128
#define GBK 64
#define LROW 72                          // 64 + 8 halfs pad (144B stride)
#define TILE_B (GBM * LROW * 2)          // 18432 B per tile
#define OFF_AH 0
#define OFF_AL TILE_B
#define OFF_BH (2 * TILE_B)
#define OFF_BL (3 * TILE_B)
#define STAGE  (4 * TILE_B)              // 73728 B
#define GSMEM  (2 * STAGE)               // 147456 B
#define INV2048 4.8828125e-4f

template<int DO_AL>
__device__ __forceinline__ void cp_stage(
    uint32_t base, const __half* __restrict__ Ah, const __half* __restrict__ Al,
    const __half* __restrict__ Bh, const __half* __restrict__ Bl,
    int rowBlock, int colBlock, int K, int kt, int t)
{
    #pragma unroll
    for (int i = 0; i < 4; i++) {
        int c = t + i * 256;
        int r = c >> 3, kc = (c & 7) * 8;               // kc in halves
        uint32_t doff = (uint32_t)((r * LROW + kc) * 2);
        size_t ga = (size_t)(rowBlock + r) * K + kt + kc;
        size_t gb = (size_t)(colBlock + r) * K + kt + kc;
        CP16(base + OFF_AH + doff, Ah + ga);
        if (DO_AL) CP16(base + OFF_AL + doff, Al + ga);
        CP16(base + OFF_BH + doff, Bh + gb);
        CP16(base + OFF_BL + doff, Bl + gb);
    }
}

// C = (Ah [+ Al/2048]) @ (Bh + Bl/2048)^T, al*bl dropped (al*bh too when !DO_AL).
// EPI=1: phase-shift epilogue, split-write half C0(hi)/C1(lo*2048).
// EPI=0: z selects weights/outputs; float write.
template<int EPI, int DO_AL>
__global__ void __launch_bounds__(256, 1)
gemm_fp16(const __half* __restrict__ Ah, const __half* __restrict__ Al,
          const __half* __restrict__ Bh0, const __half* __restrict__ Bl0,
          const __half* __restrict__ Bh1, const __half* __restrict__ Bl1,
          void* __restrict__ C0v, void* __restrict__ C1v,
          int K, int N)
{
    extern __shared__ char smem_raw[];
    const uint32_t sb = smem_u32(smem_raw);
    const int t = threadIdx.x, lane = t & 31, wid = t >> 5;
    const int wn = wid & 3, wm = wid >> 2;     // 2(M) x 4(N) warps; warp tile 64x32
    const int rowBlock = blockIdx.y * GBM;
    const int colBlock = blockIdx.x * GBN;

    const __half* Bh = (EPI == 1 || blockIdx.z == 0) ? Bh0 : Bh1;
    const __half* Bl = (EPI == 1 || blockIdx.z == 0) ? Bl0 : Bl1;

    float acc_hh[4][4][4];
    float acc_x [4][4][4];
    #pragma unroll
    for (int mi = 0; mi < 4; mi++)
        #pragma unroll
        for (int ni = 0; ni < 4; ni++)
            #pragma unroll
            for (int e = 0; e < 4; e++) { acc_hh[mi][ni][e] = 0.f; acc_x[mi][ni][e] = 0.f; }

    const int NK = K / GBK;
    cp_stage<DO_AL>(sb, Ah, Al, Bh, Bl, rowBlock, colBlock, K, 0, t);
    CP_COMMIT();

    // A ldsm4 lane mapping (m16 x k16 tile): rows 0..15, col halves by lane>>4
    const int a_row = (lane & 15), a_col = ((lane >> 4) << 3);
    // B ldsm4 pairing: group g = lane>>3 -> tile (n_pair_sub = g>>1, k_half = g&1)
    const int b_row = (lane & 7);
    const int b_nsub = ((lane >> 4) & 1);          // 0 or 1 within the ni pair
    const int b_col  = (((lane >> 3) & 1) << 3);   // 0 or 8 k-offset

    for (int it = 0; it < NK; it++) {
        if (it + 1 < NK) {
            cp_stage<DO_AL>(sb + ((it + 1) & 1) * STAGE, Ah, Al, Bh, Bl,
                            rowBlock, colBlock, K, (it + 1) * GBK, t);
            CP_COMMIT();
            CP_WAIT1();
        } else {
            CP_WAIT0();
        }
        __syncthreads();

        const uint32_t base = sb + (it & 1) * STAGE;
        #pragma unroll
        for (int kk = 0; kk < GBK; kk += 16) {
            // B: 2 ldsm4 per limb -> fragments for 4 n-tiles
            uint32_t b_h[4][2], b_l[4][2];
            #pragma unroll
            for (int p = 0; p < 2; p++) {
                int row = wn * 32 + (p * 2 + b_nsub) * 8 + b_row;
                uint32_t off = (uint32_t)((row * LROW + kk + b_col) * 2);
                uint32_t r4[4];
                ldsm4(r4, base + OFF_BH + off);
                b_h[p*2][0] = r4[0]; b_h[p*2][1] = r4[1];
                b_h[p*2+1][0] = r4[2]; b_h[p*2+1][1] = r4[3];
                ldsm4(r4, base + OFF_BL + off);
                b_l[p*2][0] = r4[0]; b_l[p*2][1] = r4[1];
                b_l[p*2+1][0] = r4[2]; b_l[p*2+1][1] = r4[3];
            }
            uint32_t a_h[4][4], a_l[4][4];
            #pragma unroll
            for (int mi = 0; mi < 4; mi++) {
                int row = wm * 64 + mi * 16 + a_row;
                uint32_t off = (uint32_t)((row * LROW + kk + a_col) * 2);
                ldsm4(a_h[mi], base + OFF_AH + off);
                if (DO_AL) ldsm4(a_l[mi], base + OFF_AL + off);
            }
            // term-grouped issue: 16 independent mma between writes to same acc
            #pragma unroll
            for (int mi = 0; mi < 4; mi++)
                #pragma unroll
                for (int ni = 0; ni < 4; ni++)
                    mma16816(acc_hh[mi][ni], a_h[mi], b_h[ni]);
            #pragma unroll
            for (int mi = 0; mi < 4; mi++)
                #pragma unroll
                for (int ni = 0; ni < 4; ni++)
                    mma16816(acc_x[mi][ni], a_h[mi], b_l[ni]);
            if (DO_AL) {
                #pragma unroll
                for (int mi = 0; mi < 4; mi++)
                    #pragma unroll
                    for (int ni = 0; ni < 4; ni++)
                        mma16816(acc_x[mi][ni], a_l[mi], b_h[ni]);
            }
        }
        __syncthreads();
    }

    // ---------------- epilogue ----------------
    #pragma unroll
    for (int mi = 0; mi < 4; mi++) {
        #pragma unroll
        for (int ni = 0; ni < 4; ni++) {
            float v0 = acc_hh[mi][ni][0] + acc_x[mi][ni][0] * INV2048;
            float v1 = acc_hh[mi][ni][1] + acc_x[mi][ni][1] * INV2048;
            float v2 = acc_hh[mi][ni][2] + acc_x[mi][ni][2] * INV2048;
            float v3 = acc_hh[mi][ni][3] + acc_x[mi][ni][3] * INV2048;
            int r0 = rowBlock + wm * 64 + mi * 16 + (lane >> 2);
            int r1 = r0 + 8;
            int c  = colBlock + wn * 32 + ni * 8 + (lane & 3) * 2;
            if (EPI == 1) {
                int o = c & 511;
                if (o == 0) {
                    int ci = c >> 9;
                    float ph = 6.28318530717958647692f * (float)ci / 7.0f;
                    float p0 = cosf(ph), p1 = sinf(ph);
                    v0 *= p0; v1 *= p1; v2 *= p0; v3 *= p1;
                }
                __half* Ch = (__half*)C0v;
                __half* Cl = (__half*)C1v;
                __half h0 = __float2half_rn(v0), h1 = __float2half_rn(v1);
                __half h2 = __float2half_rn(v2), h3 = __float2half_rn(v3);
                __half l0 = __float2half_rn((v0 - __half2float(h0)) * 2048.f);
                __half l1 = __float2half_rn((v1 - __half2float(h1)) * 2048.f);
                __half l2 = __float2half_rn((v2 - __half2float(h2)) * 2048.f);
                __half l3 = __float2half_rn((v3 - __half2float(h3)) * 2048.f);
                *(__half2*)(Ch + (size_t)r0 * N + c) = __halves2half2(h0, h1);
                *(__half2*)(Ch + (size_t)r1 * N + c) = __halves2half2(h2, h3);
                *(__half2*)(Cl + (size_t)r0 * N + c) = __halves2half2(l0, l1);
                *(__half2*)(Cl + (size_t)r1 * N + c) = __halves2half2(l2, l3);
            } else {
                float* Cf = (blockIdx.z == 0) ? (float*)C0v : (float*)C1v;
                *(float2*)(Cf + (size_t)r0 * N + c) = make_float2(v0, v1);
                *(float2*)(Cf + (size_t)r1 * N + c) = make_float2(v2, v3);
            }
        }
    }
}

// ---------------- elementwise kernels ----------------
__device__ __forceinline__ float blockReduceSum(float v) {
    __shared__ float sh[33];
    int lane = threadIdx.x & 31, wid = threadIdx.x >> 5;
    #pragma unroll
    for (int o = 16; o; o >>= 1) v += __shfl_down_sync(0xffffffffu, v, o);
    if (lane == 0) sh[wid] = v;
    __syncthreads();
    if (wid == 0) {
        v = (threadIdx.x < (blockDim.x >> 5)) ? sh[lane] : 0.f;
        #pragma unroll
        for (int o = 16; o; o >>= 1) v += __shfl_down_sync(0xffffffffu, v, o);
        if (lane == 0) sh[32] = v;
    }
    __syncthreads();
    return sh[32];
}

__device__ __forceinline__ void split_store(__half* hi, __half* lo, size_t idx2, float a, float b) {
    __half ha = __float2half_rn(a), hb = __float2half_rn(b);
    __half la = __float2half_rn((a - __half2float(ha)) * 2048.f);
    __half lb = __float2half_rn((b - __half2float(hb)) * 2048.f);
    ((__half2*)hi)[idx2] = __halves2half2(ha, hb);
    ((__half2*)lo)[idx2] = __halves2half2(la, lb);
}

// fused: vesica row scale + scaled split of x
__global__ void __launch_bounds__(256) k_scale_split(const float* __restrict__ x) {
    int b  = blockIdx.x;
    int bp = (b == 0) ? (BROWS - 1) : (b - 1);
    const float4* r0 = (const float4*)(x + (size_t)b  * DIN);
    const float4* r1 = (const float4*)(x + (size_t)bp * DIN);
    float ss = 0.f;
    float4 va[2];
    #pragma unroll
    for (int j = 0; j < 2; j++) {
        int i = threadIdx.x + j * 256;
        float4 a = r0[i], c = r1[i];
        va[j] = a;
        float dx = a.x - c.x, dy = a.y - c.y, dz = a.z - c.z, dw = a.w - c.w;
        ss += dx*dx + dy*dy + dz*dz + dw*dw;
    }
    ss = blockReduceSum(ss);          // broadcast
    float dist = sqrtf(ss);
    float s = 1.f + fmaxf(0.f, 1.f - fabsf(dist - 1.f));
    size_t rowBase = (size_t)b * (DIN / 4);
    #pragma unroll
    for (int j = 0; j < 2; j++) {
        size_t i4 = rowBase + threadIdx.x + j * 256;
        split_store(g_xh, g_xl, i4 * 2 + 0, va[j].x * s, va[j].y * s);
        split_store(g_xh, g_xl, i4 * 2 + 1, va[j].z * s, va[j].w * s);
    }
}

__global__ void __launch_bounds__(256) k_split(const float* __restrict__ src,
                                               __half* __restrict__ hi, __half* __restrict__ lo,
                                               size_t n4) {
    size_t i = (size_t)blockIdx.x * 256 + threadIdx.x;
    if (i >= n4) return;
    float4 v = ((const float4*)src)[i];
    split_store(hi, lo, i * 2 + 0, v.x, v.y);
    split_store(hi, lo, i * 2 + 1, v.z, v.w);
}

__global__ void __launch_bounds__(256) k_split_flip(const float* __restrict__ src,
                                                    __half* __restrict__ hi, __half* __restrict__ lo) {
    size_t i = (size_t)blockIdx.x * 256 + threadIdx.x;   // float4 index over [DOUT, DHID]
    if (i >= (size_t)DOUT * DHID / 4) return;
    int o  = (int)(i / (DHID / 4));
    int h4 = (int)(i % (DHID / 4)) * 4;
    float4 v = *(const float4*)(src + (size_t)o * DHID + (DHID - 4 - h4));
    split_store(hi, lo, i * 2 + 0, v.w, v.z);
    split_store(hi, lo, i * 2 + 1, v.y, v.x);
}

__global__ void __launch_bounds__(256) k_final(float* __restrict__ out) {
    int b = blockIdx.x;
    const float4* mr = (const float4*)(g_male + (size_t)b * DOUT);
    const float4* fr = (const float4*)(g_fem  + (size_t)b * DOUT);
    int i0 = threadIdx.x, i1 = threadIdx.x + 256;
    float4 m0 = mr[i0], m1 = mr[i1];
    float4 f0 = fr[i0], f1 = fr[i1];
    float s = m0.x*f0.x + m0.y*f0.y + m0.z*f0.z + m0.w*f0.w
            + m1.x*f1.x + m1.y*f1.y + m1.z*f1.z + m1.w*f1.w;
    s = blockReduceSum(s);
    float pl = 1.f / (1.f + expf(-s));
    float om = 1.f - pl;
    float4* o4 = (float4*)(out + (size_t)b * DOUT);
    o4[i0] = make_float4(pl*m0.x + om*f0.x, pl*m0.y + om*f0.y,
                         pl*m0.z + om*f0.z, pl*m0.w + om*f0.w);
    o4[i1] = make_float4(pl*m1.x + om*f1.x, pl*m1.y + om*f1.y,
                         pl*m1.z + om*f1.z, pl*m1.w + om*f1.w);
}

// ---------------- launch ----------------
extern "C" void kernel_launch(void* const* d_in, const int* in_sizes, int n_in,
                              void* d_out, int out_size) {
    const float* x   = (const float*)d_in[0];   // [4096, 2048]
    const float* wfl = (const float*)d_in[1];   // [3584, 2048]
    const float* wm  = (const float*)d_in[2];   // [2048, 3584]
    const float* wfe = (const float*)d_in[3];   // [2048, 3584]
    float* out = (float*)d_out;

    __half *xh, *xl, *wflh, *wfll, *wmh, *wml, *wfh, *wfl2, *xeh, *xel;
    float *male, *fem;
    cudaGetSymbolAddress((void**)&xh,   g_xh);
    cudaGetSymbolAddress((void**)&xl,   g_xl);
    cudaGetSymbolAddress((void**)&wflh, g_wflh);
    cudaGetSymbolAddress((void**)&wfll, g_wfll);
    cudaGetSymbolAddress((void**)&wmh,  g_wmh);
    cudaGetSymbolAddress((void**)&wml,  g_wml);
    cudaGetSymbolAddress((void**)&wfh,  g_wfh);
    cudaGetSymbolAddress((void**)&wfl2, g_wfl2);
    cudaGetSymbolAddress((void**)&xeh,  g_xeh);
    cudaGetSymbolAddress((void**)&xel,  g_xel);
    cudaGetSymbolAddress((void**)&male, g_male);
    cudaGetSymbolAddress((void**)&fem,  g_fem);

    cudaFuncSetAttribute(gemm_fp16<1,0>, cudaFuncAttributeMaxDynamicSharedMemorySize, GSMEM);
    cudaFuncSetAttribute(gemm_fp16<0,1>, cudaFuncAttributeMaxDynamicSharedMemorySize, GSMEM);

    // 1) vesica scale + x split (fused) and weight splits
    k_scale_split<<<BROWS, 256>>>(x);
    k_split<<<(unsigned)(((size_t)DHID * DIN / 4 + 255) / 256), 256>>>(wfl, wflh, wfll, (size_t)DHID * DIN / 4);
    k_split<<<(unsigned)(((size_t)DOUT * DHID / 4 + 255) / 256), 256>>>(wm, wmh, wml, (size_t)DOUT * DHID / 4);
    k_split_flip<<<(unsigned)(((size_t)DOUT * DHID / 4 + 255) / 256), 256>>>(wfe, wfh, wfl2);

    // 2) GEMM1 (2-term: ah*bh + ah*bl): x_expanded with phase epilogue + split write
    {
        dim3 grid(DHID / GBN, BROWS / GBM, 1);
        gemm_fp16<1,0><<<grid, 256, GSMEM>>>(xh, xl, wflh, wfll, wflh, wfll,
                                             xeh, xel, DIN, DHID);
    }

    // 3) GEMM2 (3-term; z=0 male / z=1 female): xexp @ W^T
    {
        dim3 grid(DOUT / GBN, BROWS / GBM, 2);
        gemm_fp16<0,1><<<grid, 256, GSMEM>>>(xeh, xel, wmh, wml, wfh, wfl2,
                                             male, fem, DHID, DOUT);
    }

    // 4) phase-lock blend
    k_final<<<BROWS, 256>>>(out);
}